// round 4
// baseline (speedup 1.0000x reference)
#include <cuda_runtime.h>

#define NN    131072
#define KK    27
#define FINN  3
#define FOUTN 32
#define EPSB  1e-5f

// Scratch for intermediate h = silu(bn(gather-gemm1))  [N, 32] fp32 = 16 MB
__device__ __align__(256) float g_h[NN * FOUTN];

typedef unsigned long long ull;

__device__ __forceinline__ ull fma2(ull a, ull b, ull c) {
    ull d;
    asm("fma.rn.f32x2 %0, %1, %2, %3;" : "=l"(d) : "l"(a), "l"(b), "l"(c));
    return d;
}
__device__ __forceinline__ ull pack2(float x) {
    ull r; unsigned u = __float_as_uint(x);
    asm("mov.b64 %0, {%1, %2};" : "=l"(r) : "r"(u), "r"(u));
    return r;
}
__device__ __forceinline__ float2 unpack2(ull v) {
    unsigned lo, hi;
    asm("mov.b64 {%0, %1}, %2;" : "=r"(lo), "=r"(hi) : "l"(v));
    return make_float2(__uint_as_float(lo), __uint_as_float(hi));
}

// ============================================================================
// Stage 1: h[n,:] = silu(bn1( sum_k sum_f x[nbr[n,k],f] * w1[k,f,:] ))
// one thread per node, 16 f32x2 accumulators, w1 in static SMEM
// ============================================================================
__global__ __launch_bounds__(256)
void stage1_kernel(const float* __restrict__ x_feats,
                   const int*   __restrict__ nbr,
                   const float* __restrict__ w1,
                   const float* __restrict__ gamma1,
                   const float* __restrict__ beta1,
                   const float* __restrict__ mean1,
                   const float* __restrict__ var1)
{
    __shared__ __align__(16) float w1s[KK * FINN * FOUTN];   // 2592 floats
    __shared__ float s_scale[FOUTN], s_shift[FOUTN];

    const int tid = threadIdx.x;
    for (int i = tid; i < (KK * FINN * FOUTN) / 4; i += blockDim.x)
        ((float4*)w1s)[i] = ((const float4*)w1)[i];
    if (tid < FOUTN) {
        float sc = gamma1[tid] * rsqrtf(var1[tid] + EPSB);
        s_scale[tid] = sc;
        s_shift[tid] = beta1[tid] - mean1[tid] * sc;
    }
    __syncthreads();

    const int n = blockIdx.x * blockDim.x + tid;
    const int* nrow = nbr + (size_t)n * KK;

    ull acc[16];
    #pragma unroll
    for (int i = 0; i < 16; i++) acc[i] = 0ULL;

    int idx_next = nrow[0];
    #pragma unroll 1
    for (int k = 0; k < KK; k++) {
        const int idx = idx_next;
        if (k + 1 < KK) idx_next = nrow[k + 1];
        const float* xr = x_feats + (size_t)idx * FINN;
        float xv[3];
        xv[0] = xr[0]; xv[1] = xr[1]; xv[2] = xr[2];
        #pragma unroll
        for (int f = 0; f < FINN; f++) {
            ull s2 = pack2(xv[f]);
            const ulonglong2* wp = (const ulonglong2*)(w1s + (k * FINN + f) * FOUTN);
            #pragma unroll
            for (int j = 0; j < 8; j++) {
                ulonglong2 w = wp[j];
                acc[2 * j]     = fma2(s2, w.x, acc[2 * j]);
                acc[2 * j + 1] = fma2(s2, w.y, acc[2 * j + 1]);
            }
        }
    }

    // epilogue: BN + SiLU, store h row (128B, 8x STG.128)
    float outv[FOUTN];
    #pragma unroll
    for (int i = 0; i < 16; i++) {
        float2 v = unpack2(acc[i]);
        outv[2 * i] = v.x; outv[2 * i + 1] = v.y;
    }
    float4* dst = (float4*)(g_h + (size_t)n * FOUTN);
    #pragma unroll
    for (int j = 0; j < 8; j++) {
        float4 o4;
        float v;
        v = outv[4 * j + 0] * s_scale[4 * j + 0] + s_shift[4 * j + 0];
        o4.x = v / (1.f + __expf(-v));
        v = outv[4 * j + 1] * s_scale[4 * j + 1] + s_shift[4 * j + 1];
        o4.y = v / (1.f + __expf(-v));
        v = outv[4 * j + 2] * s_scale[4 * j + 2] + s_shift[4 * j + 2];
        o4.z = v / (1.f + __expf(-v));
        v = outv[4 * j + 3] * s_scale[4 * j + 3] + s_shift[4 * j + 3];
        o4.w = v / (1.f + __expf(-v));
        dst[j] = o4;
    }
}

// ============================================================================
// Stage 2: x_out[n,:] = sum_k h[nbr[n,k],:] @ w2[k,:,:]; fuse point branch.
// one thread per node, 16 f32x2 accumulators, full w2 (108 KB) in dyn SMEM
// ============================================================================
#define SMEM2_FLOATS (KK * FOUTN * FOUTN + 96 + 32)
#define SMEM2_BYTES  (SMEM2_FLOATS * 4)

__global__ __launch_bounds__(256, 2)
void stage2_kernel(const float* __restrict__ z_feats,
                   const int*   __restrict__ nbr,
                   const float* __restrict__ w2,
                   const float* __restrict__ mlp_w,
                   const float* __restrict__ mlp_b,
                   const float* __restrict__ mlp_gamma,
                   const float* __restrict__ mlp_beta,
                   const float* __restrict__ mlp_mean,
                   const float* __restrict__ mlp_var,
                   float* __restrict__ out,
                   int N, int copies)
{
    extern __shared__ __align__(16) float smem2[];
    float* w2s = smem2;                          // 27648 floats
    float* zw  = smem2 + KK * FOUTN * FOUTN;     // 96 floats (bn-folded mlp_w)
    float* zb  = zw + 96;                        // 32 floats (bn-folded bias)

    const int tid = threadIdx.x;
    for (int i = tid; i < (KK * FOUTN * FOUTN) / 4; i += blockDim.x)
        ((float4*)w2s)[i] = ((const float4*)w2)[i];
    if (tid < FOUTN) {
        float sc = mlp_gamma[tid] * rsqrtf(mlp_var[tid] + EPSB);
        float sh = mlp_beta[tid] - mlp_mean[tid] * sc;
        zb[tid] = mlp_b[tid] * sc + sh;
        #pragma unroll
        for (int f = 0; f < FINN; f++)
            zw[f * FOUTN + tid] = mlp_w[f * FOUTN + tid] * sc;
    }
    __syncthreads();

    const int n = blockIdx.x * blockDim.x + tid;
    const int* nrow = nbr + (size_t)n * KK;

    ull acc[16];
    #pragma unroll
    for (int i = 0; i < 16; i++) acc[i] = 0ULL;

    int idx_next = nrow[0];
    #pragma unroll 1
    for (int k = 0; k < KK; k++) {
        const int idx = idx_next;
        if (k + 1 < KK) idx_next = nrow[k + 1];

        const float4* hr = (const float4*)(g_h + (size_t)idx * FOUTN);
        float hv[FOUTN];
        #pragma unroll
        for (int j = 0; j < 8; j++) {
            float4 t = hr[j];
            hv[4 * j + 0] = t.x; hv[4 * j + 1] = t.y;
            hv[4 * j + 2] = t.z; hv[4 * j + 3] = t.w;
        }

        const float* wk = w2s + k * FOUTN * FOUTN;
        #pragma unroll
        for (int f = 0; f < FOUTN; f++) {
            ull s2 = pack2(hv[f]);
            const ulonglong2* wp = (const ulonglong2*)(wk + f * FOUTN);
            #pragma unroll
            for (int j = 0; j < 8; j++) {
                ulonglong2 w = wp[j];
                acc[2 * j]     = fma2(s2, w.x, acc[2 * j]);
                acc[2 * j + 1] = fma2(s2, w.y, acc[2 * j + 1]);
            }
        }
    }

    // epilogue: point branch z = relu(bn(z_feats@W+b)) with bn pre-folded
    const float* zr = z_feats + (size_t)n * FINN;
    float z0 = zr[0], z1 = zr[1], z2 = zr[2];

    float outv[FOUTN];
    #pragma unroll
    for (int i = 0; i < 16; i++) {
        float2 v = unpack2(acc[i]);
        outv[2 * i] = v.x; outv[2 * i + 1] = v.y;
    }
    #pragma unroll
    for (int o = 0; o < FOUTN; o++) {
        float zp = z0 * zw[o] + z1 * zw[FOUTN + o] + z2 * zw[2 * FOUTN + o] + zb[o];
        outv[o] += fmaxf(zp, 0.f);
    }

    float4* dst0 = (float4*)(out + (size_t)n * FOUTN);
    #pragma unroll
    for (int j = 0; j < 8; j++)
        dst0[j] = make_float4(outv[4 * j], outv[4 * j + 1], outv[4 * j + 2], outv[4 * j + 3]);
    if (copies > 1) {
        float4* dst1 = (float4*)(out + (size_t)N * FOUTN + (size_t)n * FOUTN);
        #pragma unroll
        for (int j = 0; j < 8; j++)
            dst1[j] = make_float4(outv[4 * j], outv[4 * j + 1], outv[4 * j + 2], outv[4 * j + 3]);
    }
}

extern "C" void kernel_launch(void* const* d_in, const int* in_sizes, int n_in,
                              void* d_out, int out_size) {
    const float* x_feats   = (const float*)d_in[0];
    const float* z_feats   = (const float*)d_in[1];
    const int*   nbr       = (const int*)d_in[2];
    const float* w1        = (const float*)d_in[3];
    const float* bn1_gamma = (const float*)d_in[4];
    const float* bn1_beta  = (const float*)d_in[5];
    const float* bn1_mean  = (const float*)d_in[6];
    const float* bn1_var   = (const float*)d_in[7];
    const float* w2        = (const float*)d_in[8];
    const float* mlp_w     = (const float*)d_in[9];
    const float* mlp_b     = (const float*)d_in[10];
    const float* mlp_gamma = (const float*)d_in[11];
    const float* mlp_beta  = (const float*)d_in[12];
    const float* mlp_mean  = (const float*)d_in[13];
    const float* mlp_var   = (const float*)d_in[14];

    const int N = in_sizes[0] / FINN;
    const int copies = out_size / (N * FOUTN);

    static int smem_cfg_done = 0;
    if (!smem_cfg_done) {
        (void)cudaFuncSetAttribute(stage2_kernel,
                                   cudaFuncAttributeMaxDynamicSharedMemorySize,
                                   SMEM2_BYTES);
        smem_cfg_done = 1;
    }

    stage1_kernel<<<N / 256, 256>>>(x_feats, nbr, w1,
                                    bn1_gamma, bn1_beta, bn1_mean, bn1_var);
    stage2_kernel<<<N / 256, 256, SMEM2_BYTES>>>(z_feats, nbr, w2,
                                                 mlp_w, mlp_b, mlp_gamma, mlp_beta,
                                                 mlp_mean, mlp_var,
                                                 (float*)d_out, N, copies);
}

// round 5
// speedup vs baseline: 1.3829x; 1.3829x over previous
#include <cuda_runtime.h>

#define NN    131072
#define KK    27
#define FINN  3
#define FOUTN 32
#define EPSB  1e-5f

#define TILE2 512     // nodes per stage2 block
#define THR2  256     // threads per stage2 block (2 nodes/thread)
#define RSTRIDE 36    // staging row stride in floats (144B, 16B aligned)

// Scratch: h = silu(bn(gemm1)) [N,32] fp32 (16MB) ; x padded to 16B rows (2MB)
__device__ __align__(256) float g_h[NN * FOUTN];
__device__ __align__(256) float g_x4[NN * 4];

typedef unsigned long long ull;

__device__ __forceinline__ ull fma2(ull a, ull b, ull c) {
    ull d;
    asm("fma.rn.f32x2 %0, %1, %2, %3;" : "=l"(d) : "l"(a), "l"(b), "l"(c));
    return d;
}
__device__ __forceinline__ ull pack2(float x) {
    ull r; unsigned u = __float_as_uint(x);
    asm("mov.b64 %0, {%1, %2};" : "=l"(r) : "r"(u), "r"(u));
    return r;
}
__device__ __forceinline__ float2 unpack2(ull v) {
    unsigned lo, hi;
    asm("mov.b64 {%0, %1}, %2;" : "=r"(lo), "=r"(hi) : "l"(v));
    return make_float2(__uint_as_float(lo), __uint_as_float(hi));
}

// ============================================================================
// Repack x_feats [N,3] -> g_x4 [N,4] so stage1 gather is one LDG.128 per row
// ============================================================================
__global__ __launch_bounds__(256)
void repack_kernel(const float* __restrict__ x_feats) {
    const int n = blockIdx.x * blockDim.x + threadIdx.x;
    const float* s = x_feats + (size_t)n * 3;
    ((float4*)g_x4)[n] = make_float4(s[0], s[1], s[2], 0.f);
}

// ============================================================================
// Stage 1: h[n,:] = silu(bn1( sum_k sum_f x4[nbr[n,k]].f * w1[k,f,:] ))
// one thread per node; gather = 1 LDG.128 per (node,k)
// ============================================================================
__global__ __launch_bounds__(256)
void stage1_kernel(const int*   __restrict__ nbr,
                   const float* __restrict__ w1,
                   const float* __restrict__ gamma1,
                   const float* __restrict__ beta1,
                   const float* __restrict__ mean1,
                   const float* __restrict__ var1)
{
    __shared__ __align__(16) float w1s[KK * FINN * FOUTN];   // 2592 floats
    __shared__ float s_scale[FOUTN], s_shift[FOUTN];

    const int tid = threadIdx.x;
    for (int i = tid; i < (KK * FINN * FOUTN) / 4; i += blockDim.x)
        ((float4*)w1s)[i] = ((const float4*)w1)[i];
    if (tid < FOUTN) {
        float sc = gamma1[tid] * rsqrtf(var1[tid] + EPSB);
        s_scale[tid] = sc;
        s_shift[tid] = beta1[tid] - mean1[tid] * sc;
    }
    __syncthreads();

    const int n = blockIdx.x * blockDim.x + tid;
    const int* nrow = nbr + (size_t)n * KK;

    ull acc[16];
    #pragma unroll
    for (int i = 0; i < 16; i++) acc[i] = 0ULL;

    int idx_next = nrow[0];
    #pragma unroll 1
    for (int k = 0; k < KK; k++) {
        const int idx = idx_next;
        if (k + 1 < KK) idx_next = nrow[k + 1];
        float4 xv4 = ((const float4*)g_x4)[idx];
        float xv[3] = {xv4.x, xv4.y, xv4.z};
        #pragma unroll
        for (int f = 0; f < FINN; f++) {
            ull s2 = pack2(xv[f]);
            const ulonglong2* wp = (const ulonglong2*)(w1s + (k * FINN + f) * FOUTN);
            #pragma unroll
            for (int j = 0; j < 8; j++) {
                ulonglong2 w = wp[j];
                acc[2 * j]     = fma2(s2, w.x, acc[2 * j]);
                acc[2 * j + 1] = fma2(s2, w.y, acc[2 * j + 1]);
            }
        }
    }

    float outv[FOUTN];
    #pragma unroll
    for (int i = 0; i < 16; i++) {
        float2 v = unpack2(acc[i]);
        outv[2 * i] = v.x; outv[2 * i + 1] = v.y;
    }
    float4* dst = (float4*)(g_h + (size_t)n * FOUTN);
    #pragma unroll
    for (int j = 0; j < 8; j++) {
        float4 o4; float v;
        v = outv[4*j+0] * s_scale[4*j+0] + s_shift[4*j+0]; o4.x = v / (1.f + __expf(-v));
        v = outv[4*j+1] * s_scale[4*j+1] + s_shift[4*j+1]; o4.y = v / (1.f + __expf(-v));
        v = outv[4*j+2] * s_scale[4*j+2] + s_shift[4*j+2]; o4.z = v / (1.f + __expf(-v));
        v = outv[4*j+3] * s_scale[4*j+3] + s_shift[4*j+3]; o4.w = v / (1.f + __expf(-v));
        dst[j] = o4;
    }
}

// ============================================================================
// Stage 2: x_out[n,:] = sum_k h[nbr[n,k],:] @ w2[k,:,:]; fuse point branch.
// 256 threads x 2 nodes; cooperative SMEM-staged gather (8 lanes/row),
// register prefetch of k+1 rows during compute of k, w2 in SMEM.
// ============================================================================
#define W2_FLOATS   (KK * FOUTN * FOUTN)          // 27648
#define STG_FLOATS  (TILE2 * RSTRIDE)             // 18432
#define IDX_INTS    (2 * TILE2)                   // 1024
#define SMEM2_FLOATS (W2_FLOATS + STG_FLOATS + IDX_INTS + 96 + 32)
#define SMEM2_BYTES  (SMEM2_FLOATS * 4)

__global__ __launch_bounds__(THR2, 1)
void stage2_kernel(const float* __restrict__ z_feats,
                   const int*   __restrict__ nbr,
                   const float* __restrict__ w2,
                   const float* __restrict__ mlp_w,
                   const float* __restrict__ mlp_b,
                   const float* __restrict__ mlp_gamma,
                   const float* __restrict__ mlp_beta,
                   const float* __restrict__ mlp_mean,
                   const float* __restrict__ mlp_var,
                   float* __restrict__ out,
                   int N, int copies)
{
    extern __shared__ __align__(16) float smem2[];
    float* w2s   = smem2;                       // 27648 floats
    float* stage = smem2 + W2_FLOATS;           // 18432 floats
    int*   idxs  = (int*)(stage + STG_FLOATS);  // 1024 ints (double-buffered)
    float* zw    = (float*)(idxs + IDX_INTS);   // 96
    float* zb    = zw + 96;                     // 32

    const int t = threadIdx.x;
    for (int i = t; i < W2_FLOATS / 4; i += THR2)
        ((float4*)w2s)[i] = ((const float4*)w2)[i];
    if (t < FOUTN) {
        float sc = mlp_gamma[t] * rsqrtf(mlp_var[t] + EPSB);
        float sh = mlp_beta[t] - mlp_mean[t] * sc;
        zb[t] = mlp_b[t] * sc + sh;
        #pragma unroll
        for (int f = 0; f < FINN; f++)
            zw[f * FOUTN + t] = mlp_w[f * FOUTN + t] * sc;
    }

    const int base  = blockIdx.x * TILE2;
    const int node0 = base + t;
    const int node1 = base + THR2 + t;
    const int* nr0 = nbr + (size_t)node0 * KK;
    const int* nr1 = nbr + (size_t)node1 * KK;

    // prologue: stage idx for k=0 (buf0) and k=1 (buf1)
    int p00 = nr0[0], p01 = nr1[0], p10 = nr0[1], p11 = nr1[1];
    idxs[t]              = p00;
    idxs[THR2 + t]       = p01;
    idxs[TILE2 + t]      = p10;
    idxs[TILE2 + THR2 + t] = p11;
    __syncthreads();

    // gather k=0 rows
    {
        float4 pf[16];
        #pragma unroll
        for (int p = 0; p < 16; p++) {
            int s = p * THR2 + t; int r = s >> 3; int g = s & 7;
            pf[p] = ((const float4*)(g_h + (size_t)idxs[r] * FOUTN))[g];
        }
        #pragma unroll
        for (int p = 0; p < 16; p++) {
            int s = p * THR2 + t; int r = s >> 3; int g = s & 7;
            *(float4*)(stage + r * RSTRIDE + g * 4) = pf[p];
        }
    }
    __syncthreads();

    ull acc0[16], acc1[16];
    #pragma unroll
    for (int i = 0; i < 16; i++) { acc0[i] = 0ULL; acc1[i] = 0ULL; }

    const float* myrow0 = stage + t * RSTRIDE;
    const float* myrow1 = stage + (THR2 + t) * RSTRIDE;

    #pragma unroll 1
    for (int k = 0; k < KK; k++) {
        // issue gather LDGs for k+1 (latency hidden under compute)
        float4 pf[16];
        if (k < KK - 1) {
            const int* ib = idxs + ((k + 1) & 1) * TILE2;
            #pragma unroll
            for (int p = 0; p < 16; p++) {
                int s = p * THR2 + t; int r = s >> 3; int g = s & 7;
                pf[p] = ((const float4*)(g_h + (size_t)ib[r] * FOUTN))[g];
            }
        }
        int nxt0 = 0, nxt1 = 0;
        if (k < KK - 2) { nxt0 = nr0[k + 2]; nxt1 = nr1[k + 2]; }

        // compute k
        const float* wk = w2s + k * (FOUTN * FOUTN);
        #pragma unroll
        for (int c = 0; c < 4; c++) {
            float4 a0 = *(const float4*)(myrow0 + c * 8);
            float4 b0 = *(const float4*)(myrow0 + c * 8 + 4);
            float4 a1 = *(const float4*)(myrow1 + c * 8);
            float4 b1 = *(const float4*)(myrow1 + c * 8 + 4);
            float h0v[8] = {a0.x, a0.y, a0.z, a0.w, b0.x, b0.y, b0.z, b0.w};
            float h1v[8] = {a1.x, a1.y, a1.z, a1.w, b1.x, b1.y, b1.z, b1.w};
            #pragma unroll
            for (int ff = 0; ff < 8; ff++) {
                int f = c * 8 + ff;
                ull s0 = pack2(h0v[ff]);
                ull s1 = pack2(h1v[ff]);
                const ulonglong2* wp = (const ulonglong2*)(wk + f * FOUTN);
                #pragma unroll
                for (int j = 0; j < 8; j++) {
                    ulonglong2 w = wp[j];
                    acc0[2*j]   = fma2(s0, w.x, acc0[2*j]);
                    acc0[2*j+1] = fma2(s0, w.y, acc0[2*j+1]);
                    acc1[2*j]   = fma2(s1, w.x, acc1[2*j]);
                    acc1[2*j+1] = fma2(s1, w.y, acc1[2*j+1]);
                }
            }
        }
        __syncthreads();   // all readers done with stage / idx buf (k&1)

        if (k < KK - 1) {
            #pragma unroll
            for (int p = 0; p < 16; p++) {
                int s = p * THR2 + t; int r = s >> 3; int g = s & 7;
                *(float4*)(stage + r * RSTRIDE + g * 4) = pf[p];
            }
        }
        if (k < KK - 2) {
            int* ob = idxs + (k & 1) * TILE2;   // buf for k+2
            ob[t] = nxt0; ob[THR2 + t] = nxt1;
        }
        __syncthreads();   // staged data visible for next iter
    }

    // epilogue: point branch + writeout, both nodes
    #pragma unroll
    for (int which = 0; which < 2; which++) {
        const int n = which ? node1 : node0;
        ull* acc = which ? acc1 : acc0;
        const float* zr = z_feats + (size_t)n * FINN;
        float z0 = zr[0], z1 = zr[1], z2 = zr[2];

        float outv[FOUTN];
        #pragma unroll
        for (int i = 0; i < 16; i++) {
            float2 v = unpack2(acc[i]);
            outv[2*i] = v.x; outv[2*i+1] = v.y;
        }
        #pragma unroll
        for (int o = 0; o < FOUTN; o++) {
            float zp = z0 * zw[o] + z1 * zw[FOUTN + o] + z2 * zw[2*FOUTN + o] + zb[o];
            outv[o] += fmaxf(zp, 0.f);
        }
        float4* dst0 = (float4*)(out + (size_t)n * FOUTN);
        #pragma unroll
        for (int j = 0; j < 8; j++)
            dst0[j] = make_float4(outv[4*j], outv[4*j+1], outv[4*j+2], outv[4*j+3]);
        if (copies > 1) {
            float4* dst1 = (float4*)(out + (size_t)N * FOUTN + (size_t)n * FOUTN);
            #pragma unroll
            for (int j = 0; j < 8; j++)
                dst1[j] = make_float4(outv[4*j], outv[4*j+1], outv[4*j+2], outv[4*j+3]);
        }
    }
}

extern "C" void kernel_launch(void* const* d_in, const int* in_sizes, int n_in,
                              void* d_out, int out_size) {
    const float* x_feats   = (const float*)d_in[0];
    const float* z_feats   = (const float*)d_in[1];
    const int*   nbr       = (const int*)d_in[2];
    const float* w1        = (const float*)d_in[3];
    const float* bn1_gamma = (const float*)d_in[4];
    const float* bn1_beta  = (const float*)d_in[5];
    const float* bn1_mean  = (const float*)d_in[6];
    const float* bn1_var   = (const float*)d_in[7];
    const float* w2        = (const float*)d_in[8];
    const float* mlp_w     = (const float*)d_in[9];
    const float* mlp_b     = (const float*)d_in[10];
    const float* mlp_gamma = (const float*)d_in[11];
    const float* mlp_beta  = (const float*)d_in[12];
    const float* mlp_mean  = (const float*)d_in[13];
    const float* mlp_var   = (const float*)d_in[14];

    const int N = in_sizes[0] / FINN;
    const int copies = out_size / (N * FOUTN);

    static int cfg_done = 0;
    if (!cfg_done) {
        (void)cudaFuncSetAttribute(stage2_kernel,
                                   cudaFuncAttributeMaxDynamicSharedMemorySize,
                                   SMEM2_BYTES);
        cfg_done = 1;
    }

    repack_kernel<<<N / 256, 256>>>(x_feats);
    stage1_kernel<<<N / 256, 256>>>(nbr, w1, bn1_gamma, bn1_beta, bn1_mean, bn1_var);
    stage2_kernel<<<N / TILE2, THR2, SMEM2_BYTES>>>(z_feats, nbr, w2,
                                                    mlp_w, mlp_b, mlp_gamma, mlp_beta,
                                                    mlp_mean, mlp_var,
                                                    (float*)d_out, N, copies);
}